// round 11
// baseline (speedup 1.0000x reference)
#include <cuda_runtime.h>
#include <cuda_fp16.h>
#include <math.h>
#include <stdint.h>

// ---------------------------------------------------------------------------
// InteractionBlock v11: comp-sorted edges + in-warp segment reduction.
// Atomic floats to L2: 205M -> ~13M (16x in-warp pre-reduction).
// Prepass: hist -> scan -> scatter (counting sort by component).
// ---------------------------------------------------------------------------

#define HF   128
#define MAXN 50000
#define MAXC 2048
#define MAXE 1600000
#define NCP  2048
#define TE   256
#define NTHR 512

__device__ float g_h[MAXN * HF];
__device__ float g_comp[MAXC * HF];
__device__ float g_cnt[MAXC];
__device__ int   g_node2comp[MAXN];
__device__ int   g_hist[NCP];
__device__ int   g_cur[NCP];
__device__ int   g_srcS[MAXE];   // sorted-by-comp metadata
__device__ int   g_cmpS[MAXE];
__device__ float g_cvS[MAXE];
__device__ int   g_permE[MAXE];  // sorted pos -> original edge id (attr index)

typedef unsigned int uint32;
typedef unsigned long long ull;

// ---- smem byte offsets for k_edge ----
#define OFF_STG 0          // fp32 attr staging [256][52]          53248
#define OFF_AH  53248      // fp16 [256 e][72 k] (stride 144B)     36864
#define OFF_W1F 90112      // frag w1 [16 jp][4 t][32 l][8B]       16384
#define OFF_W2F 106496     // frag w2 [16 nt][8 j][32 l][8B]       32768
#define OFF_B1  139264     // float[128]
#define OFF_B2  139776
#define OFF_SRC 140288     // int  [2][256]
#define OFF_CMP 142336     // int  [2][256]
#define OFF_CV  144384     // float[2][256]
#define OFF_PRM 146432     // int  [2][256]
#define SMEM_E  148480

__device__ __forceinline__ float sspf(float x) {
    float ax = fabsf(x);
    return fmaxf(x, 0.0f) + log1pf(__expf(-ax)) - 0.6931471805599453f;
}
__device__ __forceinline__ float sspf_fast(float x) {
    float ax = fabsf(x);
    return fmaxf(x, 0.0f) + __logf(1.0f + __expf(-ax)) - 0.6931471805599453f;
}
__device__ __forceinline__ uint32 packh2(float x0, float x1) {
    __half2 hh = __floats2half2_rn(x0, x1);
    return *reinterpret_cast<uint32*>(&hh);
}
__device__ __forceinline__ void ldmx4(uint32& r0, uint32& r1, uint32& r2, uint32& r3,
                                      uint32 saddr) {
    asm volatile("ldmatrix.sync.aligned.m8n8.x4.shared.b16 {%0,%1,%2,%3}, [%4];"
                 : "=r"(r0), "=r"(r1), "=r"(r2), "=r"(r3) : "r"(saddr));
}
__device__ __forceinline__ void mma16816(float& d0, float& d1, float& d2, float& d3,
                                         uint32 a0, uint32 a1, uint32 a2, uint32 a3,
                                         uint32 b0, uint32 b1) {
    asm volatile("mma.sync.aligned.m16n8k16.row.col.f32.f16.f16.f32 "
                 "{%0,%1,%2,%3},{%4,%5,%6,%7},{%8,%9},{%0,%1,%2,%3};"
                 : "+f"(d0), "+f"(d1), "+f"(d2), "+f"(d3)
                 : "r"(a0), "r"(a1), "r"(a2), "r"(a3), "r"(b0), "r"(b1));
}
__device__ __forceinline__ void redv2(float* p, float x, float y) {
    asm volatile("red.global.add.v2.f32 [%0], {%1,%2};"
                 :: "l"((ull)p), "f"(x), "f"(y) : "memory");
}
__device__ __forceinline__ void cpa8(unsigned s, const void* g) {
    asm volatile("cp.async.ca.shared.global [%0], [%1], 8;" :: "r"(s), "l"(g));
}
__device__ __forceinline__ void cpa4(unsigned s, const void* g) {
    asm volatile("cp.async.ca.shared.global [%0], [%1], 4;" :: "r"(s), "l"(g));
}
#define CP_COMMIT() asm volatile("cp.async.commit_group;" ::: "memory")
#define CP_WAIT0()  asm volatile("cp.async.wait_group 0;" ::: "memory")

// ---------------------------------------------------------------------------
__global__ void k_prep(const int* __restrict__ comp_member,
                       const int* __restrict__ comp_seg, int N) {
    int i = blockIdx.x * blockDim.x + threadIdx.x;
    if (i < N) {
        int node = comp_member[i];
        int c = comp_seg[i];
        g_node2comp[node] = c;
        atomicAdd(&g_cnt[c], 1.0f);
    }
}

// ---------------------------------------------------------------------------
__global__ void k_hist(const int* __restrict__ ei, int E) {
    __shared__ int sh[NCP];
    for (int i = threadIdx.x; i < NCP; i += blockDim.x) sh[i] = 0;
    __syncthreads();
    for (int i = blockIdx.x * blockDim.x + threadIdx.x; i < E;
         i += gridDim.x * blockDim.x)
        atomicAdd(&sh[g_node2comp[ei[E + i]]], 1);
    __syncthreads();
    for (int i = threadIdx.x; i < NCP; i += blockDim.x)
        if (sh[i]) atomicAdd(&g_hist[i], sh[i]);
}

__global__ void __launch_bounds__(1024) k_scan() {
    __shared__ int a[NCP], b[NCP];
    int t = threadIdx.x;
    a[t] = g_hist[t]; a[t + 1024] = g_hist[t + 1024];
    __syncthreads();
    int* src = a; int* dst = b;
    for (int off = 1; off < NCP; off <<= 1) {
        for (int i = t; i < NCP; i += 1024)
            dst[i] = src[i] + ((i >= off) ? src[i - off] : 0);
        __syncthreads();
        int* tmp = src; src = dst; dst = tmp;
    }
    for (int i = t; i < NCP; i += 1024)
        g_cur[i] = (i > 0) ? src[i - 1] : 0;   // exclusive prefix
}

__global__ void k_scatter(const int* __restrict__ ei,
                          const float* __restrict__ ew, int E) {
    for (int i = blockIdx.x * blockDim.x + threadIdx.x; i < E;
         i += gridDim.x * blockDim.x) {
        int c = g_node2comp[ei[E + i]];
        int pos = atomicAdd(&g_cur[c], 1);
        g_srcS[pos] = ei[i];
        g_cmpS[pos] = c;
        float w = ew[i];
        g_cvS[pos] = 10.0f / (1e-10f + w * w) - 1.0f;
        g_permE[pos] = i;
    }
}

// ---------------------------------------------------------------------------
// h = x @ lin1_w^T (fp32, unchanged)
__global__ void __launch_bounds__(256) k_h(const float* __restrict__ x,
                                           const float* __restrict__ lin1_w,
                                           int N) {
    extern __shared__ float smf[];
    float* wT = smf;
    float* xs = smf + 128 * 129;
    int tid = threadIdx.x;

    for (int idx = tid; idx < 128 * 128; idx += 256) {
        int f = idx >> 7, k = idx & 127;
        wT[k * 129 + f] = lin1_w[idx];
    }
    int n0 = blockIdx.x * 64;
    for (int idx = tid; idx < 64 * 128; idx += 256) {
        int n = idx >> 7, k = idx & 127;
        int gn = n0 + n;
        xs[idx] = (gn < N) ? x[(size_t)gn * HF + k] : 0.0f;
    }
    __syncthreads();

    int f = tid & 127;
    int no = tid >> 7;
#pragma unroll
    for (int grp = 0; grp < 8; ++grp) {
        int e0 = no + 2 * (grp * 4);
        float a0 = 0.f, a1 = 0.f, a2 = 0.f, a3 = 0.f;
#pragma unroll 4
        for (int k4 = 0; k4 < 32; ++k4) {
            float w0 = wT[(4 * k4 + 0) * 129 + f];
            float w1 = wT[(4 * k4 + 1) * 129 + f];
            float w2 = wT[(4 * k4 + 2) * 129 + f];
            float w3 = wT[(4 * k4 + 3) * 129 + f];
            float4 v0 = *(const float4*)&xs[(e0    ) * 128 + 4 * k4];
            float4 v1 = *(const float4*)&xs[(e0 + 2) * 128 + 4 * k4];
            float4 v2 = *(const float4*)&xs[(e0 + 4) * 128 + 4 * k4];
            float4 v3 = *(const float4*)&xs[(e0 + 6) * 128 + 4 * k4];
            a0 = fmaf(v0.x, w0, a0); a0 = fmaf(v0.y, w1, a0);
            a0 = fmaf(v0.z, w2, a0); a0 = fmaf(v0.w, w3, a0);
            a1 = fmaf(v1.x, w0, a1); a1 = fmaf(v1.y, w1, a1);
            a1 = fmaf(v1.z, w2, a1); a1 = fmaf(v1.w, w3, a1);
            a2 = fmaf(v2.x, w0, a2); a2 = fmaf(v2.y, w1, a2);
            a2 = fmaf(v2.z, w2, a2); a2 = fmaf(v2.w, w3, a2);
            a3 = fmaf(v3.x, w0, a3); a3 = fmaf(v3.y, w1, a3);
            a3 = fmaf(v3.z, w2, a3); a3 = fmaf(v3.w, w3, a3);
        }
        int gn = n0 + e0;
        if (gn     < N) g_h[(size_t)(gn    ) * HF + f] = a0;
        if (gn + 2 < N) g_h[(size_t)(gn + 2) * HF + f] = a1;
        if (gn + 4 < N) g_h[(size_t)(gn + 4) * HF + f] = a2;
        if (gn + 6 < N) g_h[(size_t)(gn + 6) * HF + f] = a3;
    }
}

// ---------------------------------------------------------------------------
__global__ void __launch_bounds__(NTHR, 1) k_edge(
    const float* __restrict__ attr,
    const float* __restrict__ w1, const float* __restrict__ b1,
    const float* __restrict__ w2, const float* __restrict__ b2,
    int E) {
    extern __shared__ char sm[];
    float* stg   = (float*)(sm + OFF_STG);
    float* b1s   = (float*)(sm + OFF_B1);
    float* b2s   = (float*)(sm + OFF_B2);
    int*   sSrc  = (int*)  (sm + OFF_SRC);
    int*   sCmp  = (int*)  (sm + OFF_CMP);
    float* sCv   = (float*)(sm + OFF_CV);
    int*   sPerm = (int*)  (sm + OFF_PRM);
    uint32 sbase = (uint32)__cvta_generic_to_shared(sm);

    const int tid = threadIdx.x;
    const int w   = tid >> 5;
    const int l   = tid & 31;
    const int g   = l >> 2;
    const int q   = l & 3;

    // ---- one-time weight staging in FRAGMENT order (hi only, 8B/entry) ----
    for (int idx = tid; idx < 2048; idx += NTHR) {
        int lane = idx & 31, t = (idx >> 5) & 3, jp = idx >> 7;
        int gg = lane >> 2, qq = lane & 3;
        int n = 8 * jp + gg;
        int k0 = 16 * t + 2 * qq;
        int k1 = k0 + 8;
        float v00 = (k0     < 50) ? w1[n * 50 + k0]     : 0.0f;
        float v01 = (k0 + 1 < 50) ? w1[n * 50 + k0 + 1] : 0.0f;
        float v10 = (k1     < 50) ? w1[n * 50 + k1]     : 0.0f;
        float v11 = (k1 + 1 < 50) ? w1[n * 50 + k1 + 1] : 0.0f;
        uint2 f;
        f.x = packh2(v00, v01);
        f.y = packh2(v10, v11);
        *(uint2*)(sm + OFF_W1F + idx * 8) = f;
    }
    for (int idx = tid; idx < 4096; idx += NTHR) {
        int lane = idx & 31, j = (idx >> 5) & 7, nt = idx >> 8;
        int gg = lane >> 2, qq = lane & 3;
        int n = 8 * nt + gg;
        int k0 = 16 * j + 2 * qq;
        int k1 = k0 + 8;
        uint2 f;
        f.x = packh2(w2[n * 128 + k0], w2[n * 128 + k0 + 1]);
        f.y = packh2(w2[n * 128 + k1], w2[n * 128 + k1 + 1]);
        *(uint2*)(sm + OFF_W2F + idx * 8) = f;
    }
    if (tid < 128) { b1s[tid] = b1[tid]; b2s[tid] = b2[tid]; }

    const int numTiles = (E + TE - 1) / TE;
    const int grid = gridDim.x;
    int tile = blockIdx.x;
    if (tile >= numTiles) return;

    // ---- prologue: perm[tile0], then attr/meta[tile0] + perm[tile0+grid] ----
    {
        int tbase = tile * TE;
        for (int i = tid; i < TE; i += NTHR) {
            int ge = tbase + i;
            if (ge < E) cpa4(sbase + OFF_PRM + i * 4, g_permE + ge);
        }
        CP_COMMIT(); CP_WAIT0();
        __syncthreads();
        for (int i = tid; i < TE * 25; i += NTHR) {
            int e = i / 25, ch = i - e * 25;
            int ge = tbase + e;
            if (ge < E)
                cpa8(sbase + OFF_STG + e * 208 + ch * 8,
                     attr + (size_t)sPerm[e] * 50 + ch * 2);
        }
        if (tid < TE) {
            int ge = tbase + tid;
            if (ge < E) {
                cpa4(sbase + OFF_SRC + tid * 4, g_srcS + ge);
                cpa4(sbase + OFF_CMP + tid * 4, g_cmpS + ge);
                cpa4(sbase + OFF_CV  + tid * 4, g_cvS + ge);
            }
            int ge2 = (tile + grid) * TE + tid;
            if (ge2 < E) cpa4(sbase + OFF_PRM + 1024 + tid * 4, g_permE + ge2);
        }
        CP_COMMIT();
    }

    int buf = 0;
    for (; tile < numTiles; tile += grid) {
        int ntile = tile + grid;
        int nb = buf ^ 1;
        CP_WAIT0();
        __syncthreads();   // attr[t] in STG, meta[t][buf], perm[t+grid] ready

        int ebase = tile * TE;
        // tail zero-fill (only last partial tile)
        if (ebase + TE > E && tid < TE) {
            if (ebase + tid >= E) {
                sSrc[buf * TE + tid] = 0;
                sCmp[buf * TE + tid] = 0;
                sCv [buf * TE + tid] = 0.0f;
            }
        }
        // ---- convert attr fp32 -> fp16 into AH ----
        for (int i = tid; i < TE * 32; i += NTHR) {
            int row = i >> 5, kp = i & 31;
            int k = 2 * kp;
            float v0 = 0.f, v1 = 0.f;
            if (ebase + row < E && k < 50) {
                v0 = stg[row * 52 + k];
                v1 = (k + 1 < 50) ? stg[row * 52 + k + 1] : 0.0f;
            }
            *(uint32*)(sm + OFF_AH + row * 144 + kp * 4) = packh2(v0, v1);
        }
        __syncthreads();   // AH + meta ready; STG reads done

        // ---- load stage-1 A fragments ----
        uint32 ahf[4][4];
        {
            uint32 arow = sbase + OFF_AH + (16 * w + (l & 15)) * 144 + ((l >> 4) * 16);
#pragma unroll
            for (int t = 0; t < 4; ++t)
                ldmx4(ahf[t][0], ahf[t][1], ahf[t][2], ahf[t][3], arow + t * 32);
        }
        __syncthreads();   // AH consumed; safe to refill STG / sPerm[buf]

        // ---- prefetch next tile ----
        if (ntile < numTiles) {
            int tbase = ntile * TE;
            for (int i = tid; i < TE * 25; i += NTHR) {
                int e = i / 25, ch = i - e * 25;
                int ge = tbase + e;
                if (ge < E)
                    cpa8(sbase + OFF_STG + e * 208 + ch * 8,
                         attr + (size_t)sPerm[nb * 256 + e] * 50 + ch * 2);
            }
            if (tid < TE) {
                int ge = tbase + tid;
                if (ge < E) {
                    cpa4(sbase + OFF_SRC + (nb * TE + tid) * 4, g_srcS + ge);
                    cpa4(sbase + OFF_CMP + (nb * TE + tid) * 4, g_cmpS + ge);
                    cpa4(sbase + OFF_CV  + (nb * TE + tid) * 4, g_cvS + ge);
                }
                int ge2 = (ntile + grid) * TE + tid;
                if (ge2 < E)
                    cpa4(sbase + OFF_PRM + buf * 1024 + tid * 4, g_permE + ge2);
            }
        }
        CP_COMMIT();

        // ---- stage-2 accumulators init with bias b2 ----
        float acc2[16][4];
#pragma unroll
        for (int nt = 0; nt < 16; ++nt) {
            float2 bb = *(const float2*)&b2s[8 * nt + 2 * q];
            acc2[nt][0] = bb.x; acc2[nt][1] = bb.y;
            acc2[nt][2] = bb.x; acc2[nt][3] = bb.y;
        }

        // ---- main loop over stage-2 k-tiles ----
        for (int j = 0; j < 8; ++j) {
            float a1[2][4];
#pragma unroll
            for (int p = 0; p < 2; ++p) {
                float2 bb = *(const float2*)&b1s[16 * j + 8 * p + 2 * q];
                a1[p][0] = bb.x; a1[p][1] = bb.y;
                a1[p][2] = bb.x; a1[p][3] = bb.y;
            }
#pragma unroll
            for (int t = 0; t < 4; ++t) {
#pragma unroll
                for (int p = 0; p < 2; ++p) {
                    uint2 f = *(const uint2*)(sm + OFF_W1F
                              + ((2 * j + p) * 4 + t) * 256 + l * 8);
                    mma16816(a1[p][0], a1[p][1], a1[p][2], a1[p][3],
                             ahf[t][0], ahf[t][1], ahf[t][2], ahf[t][3], f.x, f.y);
                }
            }
            uint32 ua[4];
            ua[0] = packh2(sspf_fast(a1[0][0]), sspf_fast(a1[0][1]));
            ua[1] = packh2(sspf_fast(a1[0][2]), sspf_fast(a1[0][3]));
            ua[2] = packh2(sspf_fast(a1[1][0]), sspf_fast(a1[1][1]));
            ua[3] = packh2(sspf_fast(a1[1][2]), sspf_fast(a1[1][3]));

#pragma unroll
            for (int nt = 0; nt < 16; ++nt) {
                uint2 f = *(const uint2*)(sm + OFF_W2F + (nt * 8 + j) * 256 + l * 8);
                mma16816(acc2[nt][0], acc2[nt][1], acc2[nt][2], acc2[nt][3],
                         ua[0], ua[1], ua[2], ua[3], f.x, f.y);
            }
        }

        // ---- epilogue v11: scale, in-warp segment reduce, sparse atomics ----
        {
            const int base16 = 16 * w;
            const int e1 = base16 + g, e2 = e1 + 8;
            const int src1 = sSrc[buf * TE + e1];
            const int src2 = sSrc[buf * TE + e2];
            const float cv1 = sCv[buf * TE + e1];
            const float cv2 = sCv[buf * TE + e2];
            const float2* h1 = (const float2*)&g_h[(size_t)src1 * HF];
            const float2* h2 = (const float2*)&g_h[(size_t)src2 * HF];
            const bool uniform =
                (sCmp[buf * TE + base16] == sCmp[buf * TE + base16 + 15]);

            if (uniform) {
                float* crow = &g_comp[sCmp[buf * TE + base16] * HF];
#pragma unroll
                for (int nt = 0; nt < 16; ++nt) {
                    float2 a = h1[4 * nt + q];
                    float2 b = h2[4 * nt + q];
                    float s0 = acc2[nt][0] * cv1 * a.x + acc2[nt][2] * cv2 * b.x;
                    float s1 = acc2[nt][1] * cv1 * a.y + acc2[nt][3] * cv2 * b.y;
                    s0 += __shfl_xor_sync(0xffffffffu, s0, 4);
                    s1 += __shfl_xor_sync(0xffffffffu, s1, 4);
                    s0 += __shfl_xor_sync(0xffffffffu, s0, 8);
                    s1 += __shfl_xor_sync(0xffffffffu, s1, 8);
                    s0 += __shfl_xor_sync(0xffffffffu, s0, 16);
                    s1 += __shfl_xor_sync(0xffffffffu, s1, 16);
                    if (l < 4) redv2(crow + 8 * nt + 2 * l, s0, s1);
                }
            } else {
                const int c1 = sCmp[buf * TE + e1];
                const int c2 = sCmp[buf * TE + e2];
#pragma unroll
                for (int nt = 0; nt < 16; ++nt) {
                    float2 a = h1[4 * nt + q];
                    float2 b = h2[4 * nt + q];
                    int col = 8 * nt + 2 * q;
                    if (cv1 != 0.0f)
                        redv2(&g_comp[c1 * HF + col],
                              acc2[nt][0] * cv1 * a.x, acc2[nt][1] * cv1 * a.y);
                    if (cv2 != 0.0f)
                        redv2(&g_comp[c2 * HF + col],
                              acc2[nt][2] * cv2 * b.x, acc2[nt][3] * cv2 * b.y);
                }
            }
        }
        buf = nb;
    }
}

// ---------------------------------------------------------------------------
// Tail: mean -> lin2 -> ssp -> lin (unchanged)
__global__ void __launch_bounds__(256) k_final(
    const float* __restrict__ lin2_w, const float* __restrict__ lin2_b,
    const float* __restrict__ lin_w,  const float* __restrict__ lin_b,
    float* __restrict__ out) {
    __shared__ float sin_[16 * 128];
    __shared__ float sy[16 * 128];
    __shared__ float swT[32 * 129];
    int tid = threadIdx.x;
    int c0 = blockIdx.x * 16;

    for (int idx = tid; idx < 2048; idx += 256) {
        int c = idx >> 7;
        float cnt = g_cnt[c0 + c];
        sin_[idx] = g_comp[(c0 + c) * HF + (idx & 127)] / fmaxf(cnt, 1.0f);
    }
    __syncthreads();

    int f  = tid & 127;
    int co = tid >> 7;
    float acc[8];
#pragma unroll
    for (int j = 0; j < 8; ++j) acc[j] = lin2_b[f];
    for (int kb = 0; kb < 4; ++kb) {
        __syncthreads();
        for (int idx = tid; idx < 4096; idx += 256) {
            int f_ = idx >> 5, kk = idx & 31;
            swT[kk * 129 + f_] = lin2_w[f_ * 128 + kb * 32 + kk];
        }
        __syncthreads();
        for (int kk = 0; kk < 32; ++kk) {
            float wv = swT[kk * 129 + f];
#pragma unroll
            for (int j = 0; j < 8; ++j)
                acc[j] = fmaf(sin_[(co + 2 * j) * 128 + kb * 32 + kk], wv, acc[j]);
        }
    }
#pragma unroll
    for (int j = 0; j < 8; ++j)
        sy[(co + 2 * j) * 128 + f] = sspf(acc[j]);

    float acc2[8];
#pragma unroll
    for (int j = 0; j < 8; ++j) acc2[j] = lin_b[f];
    for (int kb = 0; kb < 4; ++kb) {
        __syncthreads();
        for (int idx = tid; idx < 4096; idx += 256) {
            int f_ = idx >> 5, kk = idx & 31;
            swT[kk * 129 + f_] = lin_w[f_ * 128 + kb * 32 + kk];
        }
        __syncthreads();
        for (int kk = 0; kk < 32; ++kk) {
            float wv = swT[kk * 129 + f];
#pragma unroll
            for (int j = 0; j < 8; ++j)
                acc2[j] = fmaf(sy[(co + 2 * j) * 128 + kb * 32 + kk], wv, acc2[j]);
        }
    }
#pragma unroll
    for (int j = 0; j < 8; ++j)
        out[(size_t)(c0 + co + 2 * j) * HF + f] = acc2[j];
}

// ---------------------------------------------------------------------------
extern "C" void kernel_launch(void* const* d_in, const int* in_sizes, int n_in,
                              void* d_out, int out_size) {
    const float* x        = (const float*)d_in[0];
    const int*   ei       = (const int*)  d_in[1];
    const float* ew       = (const float*)d_in[2];
    const float* attr     = (const float*)d_in[3];
    const int*   cmember  = (const int*)  d_in[4];
    const int*   cseg     = (const int*)  d_in[5];
    const float* mlp_w1   = (const float*)d_in[6];
    const float* mlp_b1   = (const float*)d_in[7];
    const float* mlp_w2   = (const float*)d_in[8];
    const float* mlp_b2   = (const float*)d_in[9];
    const float* lin1_w   = (const float*)d_in[10];
    const float* lin2_w   = (const float*)d_in[11];
    const float* lin2_b   = (const float*)d_in[12];
    const float* lin_w    = (const float*)d_in[13];
    const float* lin_b    = (const float*)d_in[14];
    float* out = (float*)d_out;

    int N = in_sizes[0] / HF;
    int E = in_sizes[2];
    int NC = out_size / HF;

    void *p_comp, *p_cnt, *p_hist;
    cudaGetSymbolAddress(&p_comp, g_comp);
    cudaGetSymbolAddress(&p_cnt, g_cnt);
    cudaGetSymbolAddress(&p_hist, g_hist);
    cudaMemsetAsync(p_comp, 0, (size_t)NC * HF * sizeof(float));
    cudaMemsetAsync(p_cnt, 0, (size_t)NC * sizeof(float));
    cudaMemsetAsync(p_hist, 0, NCP * sizeof(int));

    int sms = 148;
    int dev = 0;
    cudaGetDevice(&dev);
    cudaDeviceGetAttribute(&sms, cudaDevAttrMultiProcessorCount, dev);

    const int SMEM_H = (128 * 129 + 64 * 128) * 4;
    cudaFuncSetAttribute(k_h, cudaFuncAttributeMaxDynamicSharedMemorySize, SMEM_H);
    cudaFuncSetAttribute(k_edge, cudaFuncAttributeMaxDynamicSharedMemorySize, SMEM_E);

    int numTiles = (E + TE - 1) / TE;
    int grid = sms < numTiles ? sms : numTiles;

    k_prep<<<(N + 255) / 256, 256>>>(cmember, cseg, N);
    k_hist<<<512, 256>>>(ei, E);
    k_scan<<<1, 1024>>>();
    k_scatter<<<512, 256>>>(ei, ew, E);
    k_h<<<(N + 63) / 64, 256, SMEM_H>>>(x, lin1_w, N);
    k_edge<<<grid, NTHR, SMEM_E>>>(attr, mlp_w1, mlp_b1, mlp_w2, mlp_b2, E);
    k_final<<<NC / 16, 256>>>(lin2_w, lin2_b, lin_w, lin_b, out);
}

// round 12
// speedup vs baseline: 1.1601x; 1.1601x over previous
#include <cuda_runtime.h>
#include <cuda_fp16.h>
#include <math.h>
#include <stdint.h>

// ---------------------------------------------------------------------------
// InteractionBlock v12: v10 base (no sort) + fp16 h + cp.async h-row gather
// into smem hidden under the MMA phase; epilogue reads h from smem.
// ---------------------------------------------------------------------------

#define HF   128
#define MAXN 50000
#define MAXC 2048
#define TE   256
#define NTHR 512

__device__ __half g_hh[MAXN * HF];
__device__ float g_comp[MAXC * HF];
__device__ float g_cnt[MAXC];
__device__ int   g_node2comp[MAXN];

typedef unsigned int uint32;
typedef unsigned long long ull;

// ---- smem byte offsets for k_edge ----
#define OFF_STG 0          // fp32 attr staging [256][52]          53248
#define OFF_AH  53248      // fp16 [256 e][72 k] (stride 144B)     36864
#define OFF_W1F 90112      // frag w1 [16 jp][4 t][32 l][8B]       16384
#define OFF_W2F 106496     // frag w2 [16 nt][8 j][32 l][8B]       32768
#define OFF_B1  139264     // float[128]
#define OFF_B2  139776
#define OFF_SRC 140288     // int  [2][256]
#define OFF_CMP 142336     // int  [2][256]
#define OFF_CV  144384     // float[2][256]
#define OFF_HS  146432     // fp16 h rows [256][272B]              69632
#define SMEM_E  216064

__device__ __forceinline__ float sspf(float x) {
    float ax = fabsf(x);
    return fmaxf(x, 0.0f) + log1pf(__expf(-ax)) - 0.6931471805599453f;
}
__device__ __forceinline__ float sspf_fast(float x) {
    float ax = fabsf(x);
    return fmaxf(x, 0.0f) + __logf(1.0f + __expf(-ax)) - 0.6931471805599453f;
}
__device__ __forceinline__ uint32 packh2(float x0, float x1) {
    __half2 hh = __floats2half2_rn(x0, x1);
    return *reinterpret_cast<uint32*>(&hh);
}
__device__ __forceinline__ void ldmx4(uint32& r0, uint32& r1, uint32& r2, uint32& r3,
                                      uint32 saddr) {
    asm volatile("ldmatrix.sync.aligned.m8n8.x4.shared.b16 {%0,%1,%2,%3}, [%4];"
                 : "=r"(r0), "=r"(r1), "=r"(r2), "=r"(r3) : "r"(saddr));
}
__device__ __forceinline__ void mma16816(float& d0, float& d1, float& d2, float& d3,
                                         uint32 a0, uint32 a1, uint32 a2, uint32 a3,
                                         uint32 b0, uint32 b1) {
    asm volatile("mma.sync.aligned.m16n8k16.row.col.f32.f16.f16.f32 "
                 "{%0,%1,%2,%3},{%4,%5,%6,%7},{%8,%9},{%0,%1,%2,%3};"
                 : "+f"(d0), "+f"(d1), "+f"(d2), "+f"(d3)
                 : "r"(a0), "r"(a1), "r"(a2), "r"(a3), "r"(b0), "r"(b1));
}
__device__ __forceinline__ void redv4(float* p, float a, float b, float c, float d) {
    asm volatile("red.global.add.v4.f32 [%0], {%1,%2,%3,%4};"
                 :: "l"(p), "f"(a), "f"(b), "f"(c), "f"(d) : "memory");
}
__device__ __forceinline__ void cpa16(unsigned s, const void* g) {
    asm volatile("cp.async.ca.shared.global [%0], [%1], 16;" :: "r"(s), "l"(g));
}
__device__ __forceinline__ void cpa8(unsigned s, const void* g) {
    asm volatile("cp.async.ca.shared.global [%0], [%1], 8;" :: "r"(s), "l"(g));
}
__device__ __forceinline__ void cpa4(unsigned s, const void* g) {
    asm volatile("cp.async.ca.shared.global [%0], [%1], 4;" :: "r"(s), "l"(g));
}
#define CP_COMMIT() asm volatile("cp.async.commit_group;" ::: "memory")
#define CP_WAIT0()  asm volatile("cp.async.wait_group 0;" ::: "memory")
#define CP_WAIT1()  asm volatile("cp.async.wait_group 1;" ::: "memory")

// ---------------------------------------------------------------------------
__global__ void k_prep(const int* __restrict__ comp_member,
                       const int* __restrict__ comp_seg, int N) {
    int i = blockIdx.x * blockDim.x + threadIdx.x;
    if (i < N) {
        int node = comp_member[i];
        int c = comp_seg[i];
        g_node2comp[node] = c;
        atomicAdd(&g_cnt[c], 1.0f);
    }
}

// ---------------------------------------------------------------------------
// h = x @ lin1_w^T, stored as fp16
__global__ void __launch_bounds__(256) k_h(const float* __restrict__ x,
                                           const float* __restrict__ lin1_w,
                                           int N) {
    extern __shared__ float smf[];
    float* wT = smf;
    float* xs = smf + 128 * 129;
    int tid = threadIdx.x;

    for (int idx = tid; idx < 128 * 128; idx += 256) {
        int f = idx >> 7, k = idx & 127;
        wT[k * 129 + f] = lin1_w[idx];
    }
    int n0 = blockIdx.x * 64;
    for (int idx = tid; idx < 64 * 128; idx += 256) {
        int n = idx >> 7, k = idx & 127;
        int gn = n0 + n;
        xs[idx] = (gn < N) ? x[(size_t)gn * HF + k] : 0.0f;
    }
    __syncthreads();

    int f = tid & 127;
    int no = tid >> 7;
#pragma unroll
    for (int grp = 0; grp < 8; ++grp) {
        int e0 = no + 2 * (grp * 4);
        float a0 = 0.f, a1 = 0.f, a2 = 0.f, a3 = 0.f;
#pragma unroll 4
        for (int k4 = 0; k4 < 32; ++k4) {
            float w0 = wT[(4 * k4 + 0) * 129 + f];
            float w1 = wT[(4 * k4 + 1) * 129 + f];
            float w2 = wT[(4 * k4 + 2) * 129 + f];
            float w3 = wT[(4 * k4 + 3) * 129 + f];
            float4 v0 = *(const float4*)&xs[(e0    ) * 128 + 4 * k4];
            float4 v1 = *(const float4*)&xs[(e0 + 2) * 128 + 4 * k4];
            float4 v2 = *(const float4*)&xs[(e0 + 4) * 128 + 4 * k4];
            float4 v3 = *(const float4*)&xs[(e0 + 6) * 128 + 4 * k4];
            a0 = fmaf(v0.x, w0, a0); a0 = fmaf(v0.y, w1, a0);
            a0 = fmaf(v0.z, w2, a0); a0 = fmaf(v0.w, w3, a0);
            a1 = fmaf(v1.x, w0, a1); a1 = fmaf(v1.y, w1, a1);
            a1 = fmaf(v1.z, w2, a1); a1 = fmaf(v1.w, w3, a1);
            a2 = fmaf(v2.x, w0, a2); a2 = fmaf(v2.y, w1, a2);
            a2 = fmaf(v2.z, w2, a2); a2 = fmaf(v2.w, w3, a2);
            a3 = fmaf(v3.x, w0, a3); a3 = fmaf(v3.y, w1, a3);
            a3 = fmaf(v3.z, w2, a3); a3 = fmaf(v3.w, w3, a3);
        }
        int gn = n0 + e0;
        if (gn     < N) g_hh[(size_t)(gn    ) * HF + f] = __float2half_rn(a0);
        if (gn + 2 < N) g_hh[(size_t)(gn + 2) * HF + f] = __float2half_rn(a1);
        if (gn + 4 < N) g_hh[(size_t)(gn + 4) * HF + f] = __float2half_rn(a2);
        if (gn + 6 < N) g_hh[(size_t)(gn + 6) * HF + f] = __float2half_rn(a3);
    }
}

// ---------------------------------------------------------------------------
__global__ void __launch_bounds__(NTHR, 1) k_edge(
    const int* __restrict__ ei, const float* __restrict__ ew,
    const float* __restrict__ attr,
    const float* __restrict__ w1, const float* __restrict__ b1,
    const float* __restrict__ w2, const float* __restrict__ b2,
    int E) {
    extern __shared__ char sm[];
    float* stg   = (float*)(sm + OFF_STG);
    float* b1s   = (float*)(sm + OFF_B1);
    float* b2s   = (float*)(sm + OFF_B2);
    int*   sSrc  = (int*)  (sm + OFF_SRC);
    int*   sCmp  = (int*)  (sm + OFF_CMP);
    float* sCv   = (float*)(sm + OFF_CV);
    uint32 sbase = (uint32)__cvta_generic_to_shared(sm);

    const int tid = threadIdx.x;
    const int w   = tid >> 5;
    const int l   = tid & 31;
    const int g   = l >> 2;
    const int q   = l & 3;

    // ---- one-time weight staging in FRAGMENT order (hi only, 8B/entry) ----
    for (int idx = tid; idx < 2048; idx += NTHR) {
        int lane = idx & 31, t = (idx >> 5) & 3, jp = idx >> 7;
        int gg = lane >> 2, qq = lane & 3;
        int n = 8 * jp + gg;
        int k0 = 16 * t + 2 * qq;
        int k1 = k0 + 8;
        float v00 = (k0     < 50) ? w1[n * 50 + k0]     : 0.0f;
        float v01 = (k0 + 1 < 50) ? w1[n * 50 + k0 + 1] : 0.0f;
        float v10 = (k1     < 50) ? w1[n * 50 + k1]     : 0.0f;
        float v11 = (k1 + 1 < 50) ? w1[n * 50 + k1 + 1] : 0.0f;
        uint2 f;
        f.x = packh2(v00, v01);
        f.y = packh2(v10, v11);
        *(uint2*)(sm + OFF_W1F + idx * 8) = f;
    }
    for (int idx = tid; idx < 4096; idx += NTHR) {
        int lane = idx & 31, j = (idx >> 5) & 7, nt = idx >> 8;
        int gg = lane >> 2, qq = lane & 3;
        int n = 8 * nt + gg;
        int k0 = 16 * j + 2 * qq;
        int k1 = k0 + 8;
        uint2 f;
        f.x = packh2(w2[n * 128 + k0], w2[n * 128 + k0 + 1]);
        f.y = packh2(w2[n * 128 + k1], w2[n * 128 + k1 + 1]);
        *(uint2*)(sm + OFF_W2F + idx * 8) = f;
    }
    if (tid < 128) { b1s[tid] = b1[tid]; b2s[tid] = b2[tid]; }

    const int numTiles = (E + TE - 1) / TE;
    int tile = blockIdx.x;
    if (tile >= numTiles) return;

    // ---- prologue prefetch of first tile (meta buf 0) ----
    {
        int tbase = tile * TE;
        for (int i = tid; i < TE * 25; i += NTHR) {
            int e = i / 25, ch = i - e * 25;
            int ge = tbase + e;
            if (ge < E)
                cpa8(sbase + OFF_STG + e * 208 + ch * 8,
                     attr + (size_t)ge * 50 + ch * 2);
        }
        if (tid < TE) {
            int ge = tbase + tid;
            if (ge < E) {
                cpa4(sbase + OFF_SRC + tid * 4, ei + ge);
                cpa4(sbase + OFF_CMP + tid * 4, ei + E + ge);
                cpa4(sbase + OFF_CV  + tid * 4, ew + ge);
            }
        }
        CP_COMMIT();
    }

    int buf = 0;
    for (; tile < numTiles; tile += gridDim.x) {
        int ntile = tile + gridDim.x;
        int nb = buf ^ 1;
        CP_WAIT0();
        __syncthreads();   // staging + meta[buf] raw ready; hs reads done

        int ebase = tile * TE;
        // ---- transform metadata in place (buf) ----
        if (tid < TE) {
            int ge = ebase + tid;
            int srcv = 0, compv = 0;
            float Cv = 0.0f;
            if (ge < E) {
                srcv = sSrc[buf * TE + tid];
                compv = g_node2comp[sCmp[buf * TE + tid]];
                float wv = sCv[buf * TE + tid];
                Cv = 10.0f / (1e-10f + wv * wv) - 1.0f;
            }
            sSrc[buf * TE + tid] = srcv;
            sCmp[buf * TE + tid] = compv;
            sCv [buf * TE + tid] = Cv;
        }
        // ---- convert attr fp32 -> fp16 into AH (single buffer) ----
        for (int i = tid; i < TE * 32; i += NTHR) {
            int row = i >> 5, kp = i & 31;
            int k = 2 * kp;
            float v0 = 0.f, v1 = 0.f;
            if (ebase + row < E && k < 50) {
                v0 = stg[row * 52 + k];
                v1 = (k + 1 < 50) ? stg[row * 52 + k + 1] : 0.0f;
            }
            *(uint32*)(sm + OFF_AH + row * 144 + kp * 4) = packh2(v0, v1);
        }
        __syncthreads();   // AH + final meta ready; staging reads done

        // ---- gather h rows for this tile into smem (group A; hidden by MMA) --
        for (int i = tid; i < TE * 16; i += NTHR) {
            int row = i >> 4, seg = i & 15;
            int src = sSrc[buf * TE + row];
            cpa16(sbase + OFF_HS + row * 272 + seg * 16,
                  g_hh + (size_t)src * HF + seg * 8);
        }
        CP_COMMIT();       // group A

        // ---- load stage-1 A fragments ----
        uint32 ahf[4][4];
        {
            uint32 arow = sbase + OFF_AH + (16 * w + (l & 15)) * 144 + ((l >> 4) * 16);
#pragma unroll
            for (int t = 0; t < 4; ++t)
                ldmx4(ahf[t][0], ahf[t][1], ahf[t][2], ahf[t][3], arow + t * 32);
        }
        // per-lane edge metadata
        const int rowe = g + ((q & 1) << 3);
        const int eIdx = 16 * w + rowe;
        const float Cv = sCv[buf * TE + eIdx];
        const int  comp = sCmp[buf * TE + eIdx];
        __syncthreads();   // AH consumed -> safe for next iteration's convert

        // ---- prefetch next tile (group B; staging now free) ----
        if (ntile < numTiles) {
            int tbase = ntile * TE;
            for (int i = tid; i < TE * 25; i += NTHR) {
                int e = i / 25, ch = i - e * 25;
                int ge = tbase + e;
                if (ge < E)
                    cpa8(sbase + OFF_STG + e * 208 + ch * 8,
                         attr + (size_t)ge * 50 + ch * 2);
            }
            if (tid < TE) {
                int ge = tbase + tid;
                if (ge < E) {
                    cpa4(sbase + OFF_SRC + (nb * TE + tid) * 4, ei + ge);
                    cpa4(sbase + OFF_CMP + (nb * TE + tid) * 4, ei + E + ge);
                    cpa4(sbase + OFF_CV  + (nb * TE + tid) * 4, ew + ge);
                }
            }
        }
        CP_COMMIT();       // group B (possibly empty)

        // ---- stage-2 accumulators init with bias b2 ----
        float acc2[16][4];
#pragma unroll
        for (int nt = 0; nt < 16; ++nt) {
            float2 bb = *(const float2*)&b2s[8 * nt + 2 * q];
            acc2[nt][0] = bb.x; acc2[nt][1] = bb.y;
            acc2[nt][2] = bb.x; acc2[nt][3] = bb.y;
        }

        // ---- main loop over stage-2 k-tiles ----
        for (int j = 0; j < 8; ++j) {
            float a1[2][4];
#pragma unroll
            for (int p = 0; p < 2; ++p) {
                float2 bb = *(const float2*)&b1s[16 * j + 8 * p + 2 * q];
                a1[p][0] = bb.x; a1[p][1] = bb.y;
                a1[p][2] = bb.x; a1[p][3] = bb.y;
            }
#pragma unroll
            for (int t = 0; t < 4; ++t) {
#pragma unroll
                for (int p = 0; p < 2; ++p) {
                    uint2 f = *(const uint2*)(sm + OFF_W1F
                              + ((2 * j + p) * 4 + t) * 256 + l * 8);
                    mma16816(a1[p][0], a1[p][1], a1[p][2], a1[p][3],
                             ahf[t][0], ahf[t][1], ahf[t][2], ahf[t][3], f.x, f.y);
                }
            }
            uint32 ua[4];
            ua[0] = packh2(sspf_fast(a1[0][0]), sspf_fast(a1[0][1]));
            ua[1] = packh2(sspf_fast(a1[0][2]), sspf_fast(a1[0][3]));
            ua[2] = packh2(sspf_fast(a1[1][0]), sspf_fast(a1[1][1]));
            ua[3] = packh2(sspf_fast(a1[1][2]), sspf_fast(a1[1][3]));

#pragma unroll
            for (int nt = 0; nt < 16; ++nt) {
                uint2 f = *(const uint2*)(sm + OFF_W2F + (nt * 8 + j) * 256 + l * 8);
                mma16816(acc2[nt][0], acc2[nt][1], acc2[nt][2], acc2[nt][3],
                         ua[0], ua[1], ua[2], ua[3], f.x, f.y);
            }
        }

        // ---- wait h-gather (group A); group B may stay in flight ----
        CP_WAIT1();
        __syncthreads();

        // ---- epilogue: shuffle pair, scale by C*h (smem), red.v4 scatter ----
        {
            float* crow = &g_comp[comp * HF];
            const bool doit = (Cv != 0.0f);
            const int podd = q & 1;
            const int p4 = (q >> 1) << 2;
#pragma unroll
            for (int nt = 0; nt < 16; ++nt) {
                float d0 = acc2[nt][0], d1 = acc2[nt][1];
                float d2 = acc2[nt][2], d3 = acc2[nt][3];
                ull send;
                if (podd) { asm("mov.b64 %0,{%1,%2};" : "=l"(send) : "f"(d0), "f"(d1)); }
                else      { asm("mov.b64 %0,{%1,%2};" : "=l"(send) : "f"(d2), "f"(d3)); }
                ull rcv = __shfl_xor_sync(0xffffffffu, send, 1);
                float rx, ry;
                asm("mov.b64 {%0,%1},%2;" : "=f"(rx), "=f"(ry) : "l"(rcv));
                float v0, v1, v2, v3;
                if (podd) { v0 = rx; v1 = ry; v2 = d2; v3 = d3; }
                else      { v0 = d0; v1 = d1; v2 = rx; v3 = ry; }
                int col0 = 8 * nt + p4;
                if (doit) {
                    uint2 hv = *(const uint2*)(sm + OFF_HS + eIdx * 272 + col0 * 2);
                    float2 f0 = __half22float2(*(__half2*)&hv.x);
                    float2 f1 = __half22float2(*(__half2*)&hv.y);
                    v0 *= Cv * f0.x; v1 *= Cv * f0.y;
                    v2 *= Cv * f1.x; v3 *= Cv * f1.y;
                    redv4(crow + col0, v0, v1, v2, v3);
                }
            }
        }
        buf = nb;
    }
}

// ---------------------------------------------------------------------------
// Tail: mean -> lin2 -> ssp -> lin (unchanged)
__global__ void __launch_bounds__(256) k_final(
    const float* __restrict__ lin2_w, const float* __restrict__ lin2_b,
    const float* __restrict__ lin_w,  const float* __restrict__ lin_b,
    float* __restrict__ out) {
    __shared__ float sin_[16 * 128];
    __shared__ float sy[16 * 128];
    __shared__ float swT[32 * 129];
    int tid = threadIdx.x;
    int c0 = blockIdx.x * 16;

    for (int idx = tid; idx < 2048; idx += 256) {
        int c = idx >> 7;
        float cnt = g_cnt[c0 + c];
        sin_[idx] = g_comp[(c0 + c) * HF + (idx & 127)] / fmaxf(cnt, 1.0f);
    }
    __syncthreads();

    int f  = tid & 127;
    int co = tid >> 7;
    float acc[8];
#pragma unroll
    for (int j = 0; j < 8; ++j) acc[j] = lin2_b[f];
    for (int kb = 0; kb < 4; ++kb) {
        __syncthreads();
        for (int idx = tid; idx < 4096; idx += 256) {
            int f_ = idx >> 5, kk = idx & 31;
            swT[kk * 129 + f_] = lin2_w[f_ * 128 + kb * 32 + kk];
        }
        __syncthreads();
        for (int kk = 0; kk < 32; ++kk) {
            float wv = swT[kk * 129 + f];
#pragma unroll
            for (int j = 0; j < 8; ++j)
                acc[j] = fmaf(sin_[(co + 2 * j) * 128 + kb * 32 + kk], wv, acc[j]);
        }
    }
#pragma unroll
    for (int j = 0; j < 8; ++j)
        sy[(co + 2 * j) * 128 + f] = sspf(acc[j]);

    float acc2[8];
#pragma unroll
    for (int j = 0; j < 8; ++j) acc2[j] = lin_b[f];
    for (int kb = 0; kb < 4; ++kb) {
        __syncthreads();
        for (int idx = tid; idx < 4096; idx += 256) {
            int f_ = idx >> 5, kk = idx & 31;
            swT[kk * 129 + f_] = lin_w[f_ * 128 + kb * 32 + kk];
        }
        __syncthreads();
        for (int kk = 0; kk < 32; ++kk) {
            float wv = swT[kk * 129 + f];
#pragma unroll
            for (int j = 0; j < 8; ++j)
                acc2[j] = fmaf(sy[(co + 2 * j) * 128 + kb * 32 + kk], wv, acc2[j]);
        }
    }
#pragma unroll
    for (int j = 0; j < 8; ++j)
        out[(size_t)(c0 + co + 2 * j) * HF + f] = acc2[j];
}

// ---------------------------------------------------------------------------
extern "C" void kernel_launch(void* const* d_in, const int* in_sizes, int n_in,
                              void* d_out, int out_size) {
    const float* x        = (const float*)d_in[0];
    const int*   ei       = (const int*)  d_in[1];
    const float* ew       = (const float*)d_in[2];
    const float* attr     = (const float*)d_in[3];
    const int*   cmember  = (const int*)  d_in[4];
    const int*   cseg     = (const int*)  d_in[5];
    const float* mlp_w1   = (const float*)d_in[6];
    const float* mlp_b1   = (const float*)d_in[7];
    const float* mlp_w2   = (const float*)d_in[8];
    const float* mlp_b2   = (const float*)d_in[9];
    const float* lin1_w   = (const float*)d_in[10];
    const float* lin2_w   = (const float*)d_in[11];
    const float* lin2_b   = (const float*)d_in[12];
    const float* lin_w    = (const float*)d_in[13];
    const float* lin_b    = (const float*)d_in[14];
    float* out = (float*)d_out;

    int N = in_sizes[0] / HF;
    int E = in_sizes[2];
    int NC = out_size / HF;

    void *p_comp, *p_cnt;
    cudaGetSymbolAddress(&p_comp, g_comp);
    cudaGetSymbolAddress(&p_cnt, g_cnt);
    cudaMemsetAsync(p_comp, 0, (size_t)NC * HF * sizeof(float));
    cudaMemsetAsync(p_cnt, 0, (size_t)NC * sizeof(float));

    int sms = 148;
    int dev = 0;
    cudaGetDevice(&dev);
    cudaDeviceGetAttribute(&sms, cudaDevAttrMultiProcessorCount, dev);

    const int SMEM_H = (128 * 129 + 64 * 128) * 4;
    cudaFuncSetAttribute(k_h, cudaFuncAttributeMaxDynamicSharedMemorySize, SMEM_H);
    cudaFuncSetAttribute(k_edge, cudaFuncAttributeMaxDynamicSharedMemorySize, SMEM_E);

    int numTiles = (E + TE - 1) / TE;
    int grid = sms < numTiles ? sms : numTiles;

    k_prep<<<(N + 255) / 256, 256>>>(cmember, cseg, N);
    k_h<<<(N + 63) / 64, 256, SMEM_H>>>(x, lin1_w, N);
    k_edge<<<grid, NTHR, SMEM_E>>>(ei, ew, attr, mlp_w1, mlp_b1,
                                   mlp_w2, mlp_b2, E);
    k_final<<<NC / 16, 256>>>(lin2_w, lin2_b, lin_w, lin_b, out);
}

// round 13
// speedup vs baseline: 1.3001x; 1.1206x over previous
#include <cuda_runtime.h>
#include <cuda_fp16.h>
#include <math.h>
#include <stdint.h>

// ---------------------------------------------------------------------------
// InteractionBlock v13: 2 CTAs/SM edge kernel.
// 256 thr / TE=128, streamed stage-2 epilogue (acc2 64 regs -> 4),
// direct-LDG attr convert, cp.async h-row gather, fp16x1 HMMA.
// ---------------------------------------------------------------------------

#define HF   128
#define MAXN 50000
#define MAXC 2048
#define TE   128
#define NTHR 256

__device__ __half g_hh[MAXN * HF];
__device__ float g_comp[MAXC * HF];
__device__ float g_cnt[MAXC];
__device__ int   g_node2comp[MAXN];

typedef unsigned int uint32;
typedef unsigned long long ull;

// ---- smem byte offsets for k_edge (total 104960 B/CTA -> 2 CTAs/SM) ----
#define OFF_AH  0          // fp16 [128 e][72 k] (stride 144B)     18432
#define OFF_W1F 18432      // frag w1 [16 jp][4 t][32 l][8B]       16384
#define OFF_W2F 34816      // frag w2 [16 nt][8 j][32 l][8B]       32768
#define OFF_B1  67584      // float[128]
#define OFF_B2  68096
#define OFF_SRC 68608      // int  [128]
#define OFF_CMP 69120
#define OFF_CV  69632
#define OFF_HS  70144      // fp16 h rows [128][272B]              34816
#define SMEM_E  104960

__device__ __forceinline__ float sspf(float x) {
    float ax = fabsf(x);
    return fmaxf(x, 0.0f) + log1pf(__expf(-ax)) - 0.6931471805599453f;
}
__device__ __forceinline__ float sspf_fast(float x) {
    float ax = fabsf(x);
    return fmaxf(x, 0.0f) + __logf(1.0f + __expf(-ax)) - 0.6931471805599453f;
}
__device__ __forceinline__ uint32 packh2(float x0, float x1) {
    __half2 hh = __floats2half2_rn(x0, x1);
    return *reinterpret_cast<uint32*>(&hh);
}
__device__ __forceinline__ void ldmx4(uint32& r0, uint32& r1, uint32& r2, uint32& r3,
                                      uint32 saddr) {
    asm volatile("ldmatrix.sync.aligned.m8n8.x4.shared.b16 {%0,%1,%2,%3}, [%4];"
                 : "=r"(r0), "=r"(r1), "=r"(r2), "=r"(r3) : "r"(saddr));
}
__device__ __forceinline__ void mma16816(float& d0, float& d1, float& d2, float& d3,
                                         uint32 a0, uint32 a1, uint32 a2, uint32 a3,
                                         uint32 b0, uint32 b1) {
    asm volatile("mma.sync.aligned.m16n8k16.row.col.f32.f16.f16.f32 "
                 "{%0,%1,%2,%3},{%4,%5,%6,%7},{%8,%9},{%0,%1,%2,%3};"
                 : "+f"(d0), "+f"(d1), "+f"(d2), "+f"(d3)
                 : "r"(a0), "r"(a1), "r"(a2), "r"(a3), "r"(b0), "r"(b1));
}
__device__ __forceinline__ void redv4(float* p, float a, float b, float c, float d) {
    asm volatile("red.global.add.v4.f32 [%0], {%1,%2,%3,%4};"
                 :: "l"(p), "f"(a), "f"(b), "f"(c), "f"(d) : "memory");
}
__device__ __forceinline__ void cpa16(unsigned s, const void* g) {
    asm volatile("cp.async.ca.shared.global [%0], [%1], 16;" :: "r"(s), "l"(g));
}
#define CP_COMMIT() asm volatile("cp.async.commit_group;" ::: "memory")
#define CP_WAIT0()  asm volatile("cp.async.wait_group 0;" ::: "memory")

// ---------------------------------------------------------------------------
__global__ void k_prep(const int* __restrict__ comp_member,
                       const int* __restrict__ comp_seg, int N) {
    int i = blockIdx.x * blockDim.x + threadIdx.x;
    if (i < N) {
        int node = comp_member[i];
        int c = comp_seg[i];
        g_node2comp[node] = c;
        atomicAdd(&g_cnt[c], 1.0f);
    }
}

// ---------------------------------------------------------------------------
// h = x @ lin1_w^T, stored as fp16
__global__ void __launch_bounds__(256) k_h(const float* __restrict__ x,
                                           const float* __restrict__ lin1_w,
                                           int N) {
    extern __shared__ float smf[];
    float* wT = smf;
    float* xs = smf + 128 * 129;
    int tid = threadIdx.x;

    for (int idx = tid; idx < 128 * 128; idx += 256) {
        int f = idx >> 7, k = idx & 127;
        wT[k * 129 + f] = lin1_w[idx];
    }
    int n0 = blockIdx.x * 64;
    for (int idx = tid; idx < 64 * 128; idx += 256) {
        int n = idx >> 7, k = idx & 127;
        int gn = n0 + n;
        xs[idx] = (gn < N) ? x[(size_t)gn * HF + k] : 0.0f;
    }
    __syncthreads();

    int f = tid & 127;
    int no = tid >> 7;
#pragma unroll
    for (int grp = 0; grp < 8; ++grp) {
        int e0 = no + 2 * (grp * 4);
        float a0 = 0.f, a1 = 0.f, a2 = 0.f, a3 = 0.f;
#pragma unroll 4
        for (int k4 = 0; k4 < 32; ++k4) {
            float w0 = wT[(4 * k4 + 0) * 129 + f];
            float w1 = wT[(4 * k4 + 1) * 129 + f];
            float w2 = wT[(4 * k4 + 2) * 129 + f];
            float w3 = wT[(4 * k4 + 3) * 129 + f];
            float4 v0 = *(const float4*)&xs[(e0    ) * 128 + 4 * k4];
            float4 v1 = *(const float4*)&xs[(e0 + 2) * 128 + 4 * k4];
            float4 v2 = *(const float4*)&xs[(e0 + 4) * 128 + 4 * k4];
            float4 v3 = *(const float4*)&xs[(e0 + 6) * 128 + 4 * k4];
            a0 = fmaf(v0.x, w0, a0); a0 = fmaf(v0.y, w1, a0);
            a0 = fmaf(v0.z, w2, a0); a0 = fmaf(v0.w, w3, a0);
            a1 = fmaf(v1.x, w0, a1); a1 = fmaf(v1.y, w1, a1);
            a1 = fmaf(v1.z, w2, a1); a1 = fmaf(v1.w, w3, a1);
            a2 = fmaf(v2.x, w0, a2); a2 = fmaf(v2.y, w1, a2);
            a2 = fmaf(v2.z, w2, a2); a2 = fmaf(v2.w, w3, a2);
            a3 = fmaf(v3.x, w0, a3); a3 = fmaf(v3.y, w1, a3);
            a3 = fmaf(v3.z, w2, a3); a3 = fmaf(v3.w, w3, a3);
        }
        int gn = n0 + e0;
        if (gn     < N) g_hh[(size_t)(gn    ) * HF + f] = __float2half_rn(a0);
        if (gn + 2 < N) g_hh[(size_t)(gn + 2) * HF + f] = __float2half_rn(a1);
        if (gn + 4 < N) g_hh[(size_t)(gn + 4) * HF + f] = __float2half_rn(a2);
        if (gn + 6 < N) g_hh[(size_t)(gn + 6) * HF + f] = __float2half_rn(a3);
    }
}

// ---------------------------------------------------------------------------
__global__ void __launch_bounds__(NTHR, 2) k_edge(
    const int* __restrict__ ei, const float* __restrict__ ew,
    const float* __restrict__ attr,
    const float* __restrict__ w1, const float* __restrict__ b1,
    const float* __restrict__ w2, const float* __restrict__ b2,
    int E) {
    extern __shared__ char sm[];
    float* b1s   = (float*)(sm + OFF_B1);
    float* b2s   = (float*)(sm + OFF_B2);
    int*   sSrc  = (int*)  (sm + OFF_SRC);
    int*   sCmp  = (int*)  (sm + OFF_CMP);
    float* sCv   = (float*)(sm + OFF_CV);
    uint32 sbase = (uint32)__cvta_generic_to_shared(sm);

    const int tid = threadIdx.x;
    const int w   = tid >> 5;         // 0..7
    const int l   = tid & 31;
    const int g   = l >> 2;
    const int q   = l & 3;

    // ---- one-time weight staging in FRAGMENT order (hi only, 8B/entry) ----
    for (int idx = tid; idx < 2048; idx += NTHR) {
        int lane = idx & 31, t = (idx >> 5) & 3, jp = idx >> 7;
        int gg = lane >> 2, qq = lane & 3;
        int n = 8 * jp + gg;
        int k0 = 16 * t + 2 * qq;
        int k1 = k0 + 8;
        float v00 = (k0     < 50) ? w1[n * 50 + k0]     : 0.0f;
        float v01 = (k0 + 1 < 50) ? w1[n * 50 + k0 + 1] : 0.0f;
        float v10 = (k1     < 50) ? w1[n * 50 + k1]     : 0.0f;
        float v11 = (k1 + 1 < 50) ? w1[n * 50 + k1 + 1] : 0.0f;
        uint2 f;
        f.x = packh2(v00, v01);
        f.y = packh2(v10, v11);
        *(uint2*)(sm + OFF_W1F + idx * 8) = f;
    }
    for (int idx = tid; idx < 4096; idx += NTHR) {
        int lane = idx & 31, j = (idx >> 5) & 7, nt = idx >> 8;
        int gg = lane >> 2, qq = lane & 3;
        int n = 8 * nt + gg;
        int k0 = 16 * j + 2 * qq;
        int k1 = k0 + 8;
        uint2 f;
        f.x = packh2(w2[n * 128 + k0], w2[n * 128 + k0 + 1]);
        f.y = packh2(w2[n * 128 + k1], w2[n * 128 + k1 + 1]);
        *(uint2*)(sm + OFF_W2F + idx * 8) = f;
    }
    if (tid < 128) { b1s[tid] = b1[tid]; b2s[tid] = b2[tid]; }
    // zero AH pad columns kp=25..31 once (never rewritten)
    for (int idx = tid; idx < 128 * 7; idx += NTHR) {
        int row = idx / 7, kp = 25 + idx % 7;
        *(uint32*)(sm + OFF_AH + row * 144 + kp * 4) = 0;
    }

    const int numTiles = (E + TE - 1) / TE;

    for (int tile = blockIdx.x; tile < numTiles; tile += gridDim.x) {
        const int ebase = tile * TE;
        __syncthreads();   // prev tile's epilogue reads of HS/meta/AH done

        // ---- metadata (direct LDG -> transform -> STS) ----
        if (tid < TE) {
            int ge = ebase + tid;
            int srcv = 0, compv = 0;
            float Cv = 0.0f;
            if (ge < E) {
                srcv = ei[ge];
                compv = g_node2comp[ei[E + ge]];
                float wv = ew[ge];
                Cv = 10.0f / (1e-10f + wv * wv) - 1.0f;
            }
            sSrc[tid] = srcv;
            sCmp[tid] = compv;
            sCv [tid] = Cv;
        }
        // ---- attr convert: direct LDG.64 -> packh2 -> STS (kp 0..24) ----
        for (int i = tid; i < TE * 25; i += NTHR) {
            int e = i / 25, ch = i - e * 25;
            int ge = ebase + e;
            uint32 v = 0;
            if (ge < E) {
                float2 a = *(const float2*)(attr + (size_t)ge * 50 + 2 * ch);
                v = packh2(a.x, a.y);
            }
            *(uint32*)(sm + OFF_AH + e * 144 + ch * 4) = v;
        }
        __syncthreads();   // AH + meta visible

        // ---- h-row gather into HS (hidden under stage-1 MMAs) ----
        for (int i = tid; i < TE * 16; i += NTHR) {
            int row = i >> 4, seg = i & 15;
            int src = sSrc[row];
            cpa16(sbase + OFF_HS + row * 272 + seg * 16,
                  g_hh + (size_t)src * HF + seg * 8);
        }
        CP_COMMIT();

        // ---- stage-1 A fragments ----
        uint32 ahf[4][4];
        {
            uint32 arow = sbase + OFF_AH + (16 * w + (l & 15)) * 144 + ((l >> 4) * 16);
#pragma unroll
            for (int t = 0; t < 4; ++t)
                ldmx4(ahf[t][0], ahf[t][1], ahf[t][2], ahf[t][3], arow + t * 32);
        }

        // ---- stage 1: hidden fragments ua[8][4] (C-frag == stage2 A-frag) ----
        uint32 ua[8][4];
#pragma unroll
        for (int j = 0; j < 8; ++j) {
            float a1[2][4];
#pragma unroll
            for (int p = 0; p < 2; ++p) {
                float2 bb = *(const float2*)&b1s[16 * j + 8 * p + 2 * q];
                a1[p][0] = bb.x; a1[p][1] = bb.y;
                a1[p][2] = bb.x; a1[p][3] = bb.y;
            }
#pragma unroll
            for (int t = 0; t < 4; ++t) {
#pragma unroll
                for (int p = 0; p < 2; ++p) {
                    uint2 f = *(const uint2*)(sm + OFF_W1F
                              + ((2 * j + p) * 4 + t) * 256 + l * 8);
                    mma16816(a1[p][0], a1[p][1], a1[p][2], a1[p][3],
                             ahf[t][0], ahf[t][1], ahf[t][2], ahf[t][3], f.x, f.y);
                }
            }
            ua[j][0] = packh2(sspf_fast(a1[0][0]), sspf_fast(a1[0][1]));
            ua[j][1] = packh2(sspf_fast(a1[0][2]), sspf_fast(a1[0][3]));
            ua[j][2] = packh2(sspf_fast(a1[1][0]), sspf_fast(a1[1][1]));
            ua[j][3] = packh2(sspf_fast(a1[1][2]), sspf_fast(a1[1][3]));
        }

        // ---- wait h-gather, then stream stage 2 + epilogue per n-tile ----
        CP_WAIT0();
        __syncthreads();

        const int rowe = g + ((q & 1) << 3);
        const int eIdx = 16 * w + rowe;
        const float Cv = sCv[eIdx];
        float* crow = &g_comp[sCmp[eIdx] * HF];
        const bool doit = (Cv != 0.0f);
        const int podd = q & 1;
        const int p4 = (q >> 1) << 2;

#pragma unroll
        for (int nt = 0; nt < 16; ++nt) {
            float d0, d1, d2, d3;
            {
                float2 bb = *(const float2*)&b2s[8 * nt + 2 * q];
                d0 = bb.x; d1 = bb.y; d2 = bb.x; d3 = bb.y;
            }
#pragma unroll
            for (int j = 0; j < 8; ++j) {
                uint2 f = *(const uint2*)(sm + OFF_W2F + (nt * 8 + j) * 256 + l * 8);
                mma16816(d0, d1, d2, d3,
                         ua[j][0], ua[j][1], ua[j][2], ua[j][3], f.x, f.y);
            }
            // shuffle pair -> row-major 4 cols, scale, scatter
            ull send;
            if (podd) { asm("mov.b64 %0,{%1,%2};" : "=l"(send) : "f"(d0), "f"(d1)); }
            else      { asm("mov.b64 %0,{%1,%2};" : "=l"(send) : "f"(d2), "f"(d3)); }
            ull rcv = __shfl_xor_sync(0xffffffffu, send, 1);
            float rx, ry;
            asm("mov.b64 {%0,%1},%2;" : "=f"(rx), "=f"(ry) : "l"(rcv));
            float v0, v1, v2, v3;
            if (podd) { v0 = rx; v1 = ry; v2 = d2; v3 = d3; }
            else      { v0 = d0; v1 = d1; v2 = rx; v3 = ry; }
            int col0 = 8 * nt + p4;
            if (doit) {
                uint2 hv = *(const uint2*)(sm + OFF_HS + eIdx * 272 + col0 * 2);
                float2 f0 = __half22float2(*(__half2*)&hv.x);
                float2 f1 = __half22float2(*(__half2*)&hv.y);
                v0 *= Cv * f0.x; v1 *= Cv * f0.y;
                v2 *= Cv * f1.x; v3 *= Cv * f1.y;
                redv4(crow + col0, v0, v1, v2, v3);
            }
        }
    }
}

// ---------------------------------------------------------------------------
// Tail: mean -> lin2 -> ssp -> lin (unchanged)
__global__ void __launch_bounds__(256) k_final(
    const float* __restrict__ lin2_w, const float* __restrict__ lin2_b,
    const float* __restrict__ lin_w,  const float* __restrict__ lin_b,
    float* __restrict__ out) {
    __shared__ float sin_[16 * 128];
    __shared__ float sy[16 * 128];
    __shared__ float swT[32 * 129];
    int tid = threadIdx.x;
    int c0 = blockIdx.x * 16;

    for (int idx = tid; idx < 2048; idx += 256) {
        int c = idx >> 7;
        float cnt = g_cnt[c0 + c];
        sin_[idx] = g_comp[(c0 + c) * HF + (idx & 127)] / fmaxf(cnt, 1.0f);
    }
    __syncthreads();

    int f  = tid & 127;
    int co = tid >> 7;
    float acc[8];
#pragma unroll
    for (int j = 0; j < 8; ++j) acc[j] = lin2_b[f];
    for (int kb = 0; kb < 4; ++kb) {
        __syncthreads();
        for (int idx = tid; idx < 4096; idx += 256) {
            int f_ = idx >> 5, kk = idx & 31;
            swT[kk * 129 + f_] = lin2_w[f_ * 128 + kb * 32 + kk];
        }
        __syncthreads();
        for (int kk = 0; kk < 32; ++kk) {
            float wv = swT[kk * 129 + f];
#pragma unroll
            for (int j = 0; j < 8; ++j)
                acc[j] = fmaf(sin_[(co + 2 * j) * 128 + kb * 32 + kk], wv, acc[j]);
        }
    }
#pragma unroll
    for (int j = 0; j < 8; ++j)
        sy[(co + 2 * j) * 128 + f] = sspf(acc[j]);

    float acc2[8];
#pragma unroll
    for (int j = 0; j < 8; ++j) acc2[j] = lin_b[f];
    for (int kb = 0; kb < 4; ++kb) {
        __syncthreads();
        for (int idx = tid; idx < 4096; idx += 256) {
            int f_ = idx >> 5, kk = idx & 31;
            swT[kk * 129 + f_] = lin_w[f_ * 128 + kb * 32 + kk];
        }
        __syncthreads();
        for (int kk = 0; kk < 32; ++kk) {
            float wv = swT[kk * 129 + f];
#pragma unroll
            for (int j = 0; j < 8; ++j)
                acc2[j] = fmaf(sy[(co + 2 * j) * 128 + kb * 32 + kk], wv, acc2[j]);
        }
    }
#pragma unroll
    for (int j = 0; j < 8; ++j)
        out[(size_t)(c0 + co + 2 * j) * HF + f] = acc2[j];
}

// ---------------------------------------------------------------------------
extern "C" void kernel_launch(void* const* d_in, const int* in_sizes, int n_in,
                              void* d_out, int out_size) {
    const float* x        = (const float*)d_in[0];
    const int*   ei       = (const int*)  d_in[1];
    const float* ew       = (const float*)d_in[2];
    const float* attr     = (const float*)d_in[3];
    const int*   cmember  = (const int*)  d_in[4];
    const int*   cseg     = (const int*)  d_in[5];
    const float* mlp_w1   = (const float*)d_in[6];
    const float* mlp_b1   = (const float*)d_in[7];
    const float* mlp_w2   = (const float*)d_in[8];
    const float* mlp_b2   = (const float*)d_in[9];
    const float* lin1_w   = (const float*)d_in[10];
    const float* lin2_w   = (const float*)d_in[11];
    const float* lin2_b   = (const float*)d_in[12];
    const float* lin_w    = (const float*)d_in[13];
    const float* lin_b    = (const float*)d_in[14];
    float* out = (float*)d_out;

    int N = in_sizes[0] / HF;
    int E = in_sizes[2];
    int NC = out_size / HF;

    void *p_comp, *p_cnt;
    cudaGetSymbolAddress(&p_comp, g_comp);
    cudaGetSymbolAddress(&p_cnt, g_cnt);
    cudaMemsetAsync(p_comp, 0, (size_t)NC * HF * sizeof(float));
    cudaMemsetAsync(p_cnt, 0, (size_t)NC * sizeof(float));

    int sms = 148;
    int dev = 0;
    cudaGetDevice(&dev);
    cudaDeviceGetAttribute(&sms, cudaDevAttrMultiProcessorCount, dev);

    const int SMEM_H = (128 * 129 + 64 * 128) * 4;
    cudaFuncSetAttribute(k_h, cudaFuncAttributeMaxDynamicSharedMemorySize, SMEM_H);
    cudaFuncSetAttribute(k_edge, cudaFuncAttributeMaxDynamicSharedMemorySize, SMEM_E);

    int numTiles = (E + TE - 1) / TE;
    int grid = 2 * sms < numTiles ? 2 * sms : numTiles;

    k_prep<<<(N + 255) / 256, 256>>>(cmember, cseg, N);
    k_h<<<(N + 63) / 64, 256, SMEM_H>>>(x, lin1_w, N);
    k_edge<<<grid, NTHR, SMEM_E>>>(ei, ew, attr, mlp_w1, mlp_b1,
                                   mlp_w2, mlp_b2, E);
    k_final<<<NC / 16, 256>>>(lin2_w, lin2_b, lin_w, lin_b, out);
}